// round 10
// baseline (speedup 1.0000x reference)
#include <cuda_runtime.h>

#define B_ 2048
#define N_ 80
#define T_ 400
#define BN_ (B_ * N_)

// div.full.f32 — the exact instruction XLA's GPU elemental emitter uses for
// fp32 divide. Bit-exactness of the simulation hinges on this.
__device__ __forceinline__ float div_full(float a, float b) {
    float r;
    asm("div.full.f32 %0, %1, %2;" : "=f"(r) : "f"(a), "f"(b));
    return r;
}

// LIF step (reference fp32 op order; act-gate as exact predicated add).
#define STEP(vv, rff, iss, add, nn, tau, th, dr, rs, SP)                          \
    {                                                                              \
        float it_  = __fadd_rn(__fsub_rn(__fadd_rn(iss, dr), add),                 \
                               __fmul_rn(nn, 0.5f));                               \
        bool  act_ = (rff <= 0.0f);                                                \
        float dv_  = __fmul_rn(0.1f, div_full(__fadd_rn(-vv, it_), tau));          \
        if (act_) vv = __fadd_rn(vv, dv_);                                         \
        SP = (vv >= th) && act_;                                                   \
        if (SP) vv = rs;                                                           \
        rff = fmaxf(__fsub_rn(SP ? 1.0f : rff, 0.1f), 0.0f);                       \
        add = __fmaf_rn(add, 0.999000499833375f, SP ? 2.0f : 0.0f);                \
    }

// Build the group-structured terms of W row j (structure fixed by the
// reference's _build_constants; weights read from W at runtime).
// dot_j = w0*popcll(mlo&L0) + w1*popcll(mlo&L1) + w2*popcll(mlo&L2)
//       + w3*popc(m2&H0)   + w4*popc(m2&H1)
__device__ __forceinline__ void build_terms(
    int j, const float* __restrict__ W,
    unsigned long long& L0, unsigned long long& L1, unsigned long long& L2,
    unsigned& H0, unsigned& H1,
    float& w0, float& w1, float& w2, float& w3, float& w4)
{
    L0 = L1 = L2 = 0ull; H0 = H1 = 0u;
    w0 = w1 = w2 = w3 = w4 = 0.0f;
    if (j < 0) return;
    const float* Wr = W + j * N_;
    const int side  = j / 40;
    const int base  = side * 40;
    const int cbase = 40 - base;
    const int r     = j - base;
#define G64(s, l) ((((1ull << (l)) - 1ull)) << (s))
#define G32H(s, l) ((unsigned)(((1u << (l)) - 1u) << ((s) - 64)))
    if (r < 5) {  // flex_rg: ->own flex(excl self)+v2a (.06), ->ext (-.4),
                  //          ->v1+v0d+fmn (2.0)
        L0 = (G64(base, 5) & ~(1ull << j)) | G64(base + 14, 3); w0 = Wr[base + 14];
        L1 = G64(base + 5, 5);                                  w1 = Wr[base + 5];
        L2 = G64(base + 10, 4) | G64(base + 21, 3);             w2 = Wr[base + 10];
        if (side == 0) L2 |= G64(30, 5);
        else { H0 = G32H(70, 5); w3 = Wr[70]; }
    } else if (r < 10) {  // ext_rg: ->flex (-.3), ->own ext(excl)+v3 (.06),
                          //         ->v2b+emn (2.0)
        L0 = G64(base, 5);                w0 = Wr[base];
        L1 = G64(base + 5, 5) & ~(1ull << j);
        w1 = Wr[base + 5 + (r == 5 ? 1 : 0)];
        L2 = G64(base + 17, 4);           w2 = Wr[base + 17];
        if (side == 0) { L1 |= G64(27, 3); L2 |= G64(35, 5); }
        else { H0 = G32H(67, 3); w3 = Wr[67];
               H1 = G32H(75, 5); w4 = Wr[75]; }
    } else if (r < 14) {  // v1 -> own emn (-3)
        if (side == 0) { L0 = G64(35, 5); w0 = Wr[35]; }
        else           { H0 = G32H(75, 5); w3 = Wr[75]; }
    } else if (r < 17) {  // v2a -> own v0v (0.4/3)
        if (side == 0) { L0 = G64(24, 3); w0 = Wr[24]; }
        else           { H0 = G32H(64, 3); w3 = Wr[64]; }
    } else if (r < 21) {  // v2b -> own fmn (-3)
        if (side == 0) { L0 = G64(30, 5); w0 = Wr[30]; }
        else           { H0 = G32H(70, 5); w3 = Wr[70]; }
    } else if (r < 24) {  // v0d -> contra flex (-3)
        L0 = G64(cbase, 5); w0 = Wr[cbase];
    } else if (r < 27) {  // v0v -> contra fmn (-0.4/3)
        if (side == 0) { H0 = G32H(70, 5); w3 = Wr[70]; }
        else           { L0 = G64(30, 5);  w0 = Wr[30]; }
    } else if (r < 30) {  // v3 -> contra ext (0.2/3)
        L0 = G64(cbase + 5, 5); w0 = Wr[cbase + 5];
    }  // mn rows: no outgoing -> all zero
#undef G64
#undef G32H
}

// One simulated timestep; PREF = compile-time prefetch toggle.
// Neuron 0 (j<32) never has H1; neuron 2 (j>=64) has only L0 — verified
// against the connection table, so those terms are omitted.
#define BODY(k, PREF)                                                              \
    {                                                                              \
        const float n0 = nb[k][0], n1 = nb[k][1], n2v = nb[k][2];                  \
        if (PREF) {                                                                \
            nb[k][0] = p0[(k) * BN_];                                              \
            nb[k][1] = p0[(k) * BN_ + 32];                                         \
            nb[k][2] = has3 ? p0[(k) * BN_ + 64] : 0.0f;                           \
        }                                                                          \
        bool sp0, sp1, sp2;                                                        \
        STEP(v0, rf0, is0, ad0, n0,  tau0, th0, dr0, rs0, sp0);                    \
        STEP(v1, rf1, is1, ad1, n1,  tau1, th1, dr1, rs1, sp1);                    \
        STEP(v2, rf2, is2, ad2, n2v, tau2, th2, dr2, rs2, sp2);                    \
        const unsigned m0 = __ballot_sync(0xffffffffu, sp0);                       \
        const unsigned m1 = __ballot_sync(0xffffffffu, sp1);                       \
        const unsigned m2 = __ballot_sync(0xffffffffu, sp2 && has3);               \
        const unsigned long long mlo = (unsigned long long)m0 |                    \
                                       ((unsigned long long)m1 << 32);             \
        float a0 = __fmaf_rn(wA0, (float)__popcll(mlo & LA0), 0.0f);               \
        a0 = __fmaf_rn(wA1, (float)__popcll(mlo & LA1), a0);                       \
        a0 = __fmaf_rn(wA2, (float)__popcll(mlo & LA2), a0);                       \
        a0 = __fmaf_rn(wA3, (float)__popc(m2 & HA0), a0);                          \
        float a1 = __fmaf_rn(wB0, (float)__popcll(mlo & LB0), 0.0f);               \
        a1 = __fmaf_rn(wB1, (float)__popcll(mlo & LB1), a1);                       \
        a1 = __fmaf_rn(wB2, (float)__popcll(mlo & LB2), a1);                       \
        a1 = __fmaf_rn(wB3, (float)__popc(m2 & HB0), a1);                          \
        a1 = __fmaf_rn(wB4, (float)__popc(m2 & HB1), a1);                          \
        float a2 = __fmaf_rn(wC0, (float)__popcll(mlo & LC0), 0.0f);               \
        is0 = __fmaf_rn(is0, decay_s, a0);                                         \
        is1 = __fmaf_rn(is1, decay_s, a1);                                         \
        is2 = __fmaf_rn(is2, decay_s, a2);                                         \
        q0[(k) * BN_] = v0;                                                        \
        q0[(k) * BN_ + 32] = v1;                                                   \
        if (has3) q0[(k) * BN_ + 64] = v2;                                         \
        float lf = __fmul_rn((float)__popcll(mlo & 0x07C0000000ull), 0.2f);        \
        float le = __fmul_rn((float)__popcll(mlo & 0xF800000000ull), 0.2f);        \
        float rfm = __fmul_rn((float)__popc(m2 & 0x000007C0u), 0.2f);              \
        float rem = __fmul_rn((float)__popc(m2 & 0x0000F800u), 0.2f);              \
        float mv = lf;                                                             \
        if (lane == 1) mv = le;                                                    \
        else if (lane == 2) mv = __fsub_rn(le, lf);                                \
        else if (lane == 3) mv = rfm;                                              \
        else if (lane == 4) mv = rem;                                              \
        else if (lane == 5) mv = __fsub_rn(rem, rfm);                              \
        if (lane < 6) mo[(k) * (B_ * 6)] = mv;                                     \
    }

__global__ void __launch_bounds__(224)
cpg_kernel(const float* __restrict__ v_in,
           const float* __restrict__ refrac_in,
           const float* __restrict__ isyn_in,
           const float* __restrict__ adapt_in,
           const float* __restrict__ noise,
           const float* __restrict__ dmod_p,
           const float* __restrict__ W,
           const float* __restrict__ tau_p,
           const float* __restrict__ vth_p,
           const float* __restrict__ tonic_p,
           const float* __restrict__ reset_p,
           float* __restrict__ v_out,
           float* __restrict__ motor_out)
{
    // one warp = one batch row; 296 blocks x 7 warps = 2072 slots (24 idle)
    const int b = blockIdx.x * 7 + (threadIdx.x >> 5);
    if (b >= B_) return;

    const float decay_s = 0.980198673306755f;  // exp(-0.1/5), correctly rounded

    const int lane = threadIdx.x & 31;
    const bool has3 = (lane < 16);
    const int j0 = lane;
    const int j1 = lane + 32;
    const int j2 = has3 ? (lane + 64) : 0;  // dummy for state loads on hi lanes

    // per-neuron group terms (registers)
    unsigned long long LA0, LA1, LA2, LB0, LB1, LB2, LC0, LC1, LC2;
    unsigned HA0, HA1, HB0, HB1, HC0, HC1;
    float wA0, wA1, wA2, wA3, wA4, wB0, wB1, wB2, wB3, wB4,
          wC0, wC1, wC2, wC3, wC4;
    build_terms(j0, W, LA0, LA1, LA2, HA0, HA1, wA0, wA1, wA2, wA3, wA4);
    build_terms(j1, W, LB0, LB1, LB2, HB0, HB1, wB0, wB1, wB2, wB3, wB4);
    build_terms(has3 ? (lane + 64) : -1, W,
                LC0, LC1, LC2, HC0, HC1, wC0, wC1, wC2, wC3, wC4);

    const float dsc = __fmaf_rn(dmod_p[0], 0.5f, 1.0f);

    const float tau0 = tau_p[j0], tau1 = tau_p[j1], tau2 = tau_p[j2];
    const float th0 = vth_p[j0], th1 = vth_p[j1];
    const float th2 = has3 ? vth_p[j2] : 3.0e38f;   // never spikes on dummy lane
    const float dr0 = __fmul_rn(tonic_p[j0], dsc);
    const float dr1 = __fmul_rn(tonic_p[j1], dsc);
    const float dr2 = __fmul_rn(tonic_p[j2], dsc);
    const float rs0 = reset_p[j0], rs1 = reset_p[j1], rs2 = reset_p[j2];

    const int base = b * N_;
    float v0 = v_in[base + j0], v1 = v_in[base + j1], v2 = has3 ? v_in[base + j2] : 0.0f;
    float rf0 = refrac_in[base + j0], rf1 = refrac_in[base + j1],
          rf2 = has3 ? refrac_in[base + j2] : 0.0f;
    float is0 = isyn_in[base + j0], is1 = isyn_in[base + j1],
          is2 = has3 ? isyn_in[base + j2] : 0.0f;
    float ad0 = adapt_in[base + j0], ad1 = adapt_in[base + j1],
          ad2 = has3 ? adapt_in[base + j2] : 0.0f;

    // streaming pointers, advanced once per 4-step group (offsets = immediates)
    const float* p0 = noise + base + j0;
    float*       q0 = v_out + base + j0;
    float*       mo = motor_out + b * 6 + lane;

    // 4-deep register ring of prefetched noise
    float nb[4][3];
#pragma unroll
    for (int k = 0; k < 4; ++k) {
        nb[k][0] = p0[k * BN_];
        nb[k][1] = p0[k * BN_ + 32];
        nb[k][2] = has3 ? p0[k * BN_ + 64] : 0.0f;
    }
    p0 += 4 * BN_;

    for (int tc = 0; tc < T_ - 4; tc += 4) {
        BODY(0, 1)
        BODY(1, 1)
        BODY(2, 1)
        BODY(3, 1)
        p0 += 4 * BN_;
        q0 += 4 * BN_;
        mo += 4 * (B_ * 6);
    }
    BODY(0, 0)
    BODY(1, 0)
    BODY(2, 0)
    BODY(3, 0)
}

extern "C" void kernel_launch(void* const* d_in, const int* in_sizes, int n_in,
                              void* d_out, int out_size)
{
    const float* v       = (const float*)d_in[0];
    const float* refrac  = (const float*)d_in[1];
    const float* i_syn   = (const float*)d_in[2];
    const float* adapt   = (const float*)d_in[3];
    const float* noise   = (const float*)d_in[4];
    const float* dmod    = (const float*)d_in[5];
    const float* W       = (const float*)d_in[6];
    const float* tau_m   = (const float*)d_in[7];
    const float* v_th    = (const float*)d_in[8];
    const float* tonic   = (const float*)d_in[9];
    const float* reset_v = (const float*)d_in[10];

    float* v_out     = (float*)d_out;                       // [T, B, N]
    float* motor_out = v_out + (size_t)T_ * B_ * N_;        // [T, B, 6]

    // 296 blocks x 7 warps: 2 blocks/SM on 148 SMs, every SM <= 14 rows
    cpg_kernel<<<296, 224>>>(v, refrac, i_syn, adapt, noise, dmod, W,
                             tau_m, v_th, tonic, reset_v, v_out, motor_out);
}